// round 8
// baseline (speedup 1.0000x reference)
#include <cuda_runtime.h>

#define NN 200000
#define EE 3200000

// ---------------- static device scratch ----------------
__device__ int      g_deg[NN];
__device__ int      g_cnt[NN];
__device__ float    g_dinv[NN];
__device__ int      g_off[NN + 1];
__device__ int      g_cur[NN];
__device__ unsigned long long g_aggr64[256];
__device__ unsigned g_gen;
__device__ int      g_src[EE];
__device__ float4   g_h[NN * 8];   // raw fp32 features
__device__ float4   g_a[NN * 8];
__device__ float4   g_t[NN * 8];
__device__ float4   g_b[NN * 8];
__device__ float4   p_h[NN * 8];   // pre-scaled (dinv*X) fp32 / P scratch
__device__ float4   p_a[NN * 8];
__device__ float4   p_t[NN * 8];
__device__ float4   p_b[NN * 8];

__device__ __forceinline__ float4* fbuf(int id) {
    switch (id) { case 0: return g_h; case 1: return g_a; case 2: return g_t; default: return g_b; }
}
__device__ __forceinline__ float4* pbuf(int id) {
    switch (id) { case 0: return p_h; case 1: return p_a; case 2: return p_t; default: return p_b; }
}
// unified buffer id: 0..3 raw, 4..7 prescaled
__device__ __forceinline__ float4* anybuf(int id) {
    return (id < 4) ? fbuf(id) : pbuf(id - 4);
}

// per-block dtype detection: 1 if edge buffer is int64
__device__ __forceinline__ int detect64(const void* ei) {
    const int* w = (const int*)ei;
    int bad = 0;
#pragma unroll
    for (int k = 0; k < 2; k++) {
        int idx = (threadIdx.x & 31) + 32 * k;
        if (w[2 * idx + 1] != 0) bad = 1;
    }
    return __all_sync(0xffffffffu, bad == 0) ? 1 : 0;
}

__device__ __forceinline__ int edge_at(const void* ei, int idx, int is64) {
    if (is64) return (int)((const long long*)ei)[idx];
    return ((const int*)ei)[idx];
}

// ---------------- count degrees ----------------
__global__ void k_count(const void* ei, int e) {
    if (blockIdx.x == 0 && threadIdx.x == 0) atomicAdd(&g_gen, 1u);
    int is64 = detect64(ei);
    int i = blockIdx.x * blockDim.x + threadIdx.x;
    if (i < e) {
        int s = edge_at(ei, i, is64);
        int d = edge_at(ei, e + i, is64);
        atomicAdd(&g_deg[s], 1);
        atomicAdd(&g_cnt[d], 1);
    }
}

// ---------------- one-kernel exclusive scan + dinv + reset ----------------
__global__ void k_scan(int n, int nb) {
    __shared__ int sh[1024];
    __shared__ int s_sum;
    int tid = threadIdx.x, b = blockIdx.x;
    int i = b * 1024 + tid;
    if (tid == 0) s_sum = 0;
    int dg = 0, v = 0;
    if (i < n) { dg = g_deg[i]; v = g_cnt[i]; }
    if (i < n) g_dinv[i] = (dg > 0) ? rsqrtf((float)dg) : 0.f;
    sh[tid] = v;
    __syncthreads();
    for (int o = 1; o < 1024; o <<= 1) {
        int t = (tid >= o) ? sh[tid - o] : 0;
        __syncthreads();
        sh[tid] += t;
        __syncthreads();
    }
    unsigned gen = g_gen;
    if (tid == 1023)
        atomicExch(&g_aggr64[b], ((unsigned long long)gen << 32) | (unsigned)sh[1023]);
    if (tid < b) {
        unsigned long long f;
        while (((f = atomicAdd(&g_aggr64[tid], 0ull)) >> 32) != gen) {}
        atomicAdd(&s_sum, (int)(unsigned)f);
    }
    __syncthreads();
    int off = sh[tid] - v + s_sum;
    if (i < n) {
        g_off[i] = off;
        g_cur[i] = off;
        g_deg[i] = 0;
        g_cnt[i] = 0;
        if (i == n - 1) g_off[n] = off + v;
    }
}

// ---------------- fused scatter + input MLP ----------------
__global__ void k_scatin(const void* ei, int e, const float* __restrict__ x,
                         const float* __restrict__ W0, const float* __restrict__ b0, int n) {
    __shared__ float sw[96];
    __shared__ float sb[32];
    int tid = threadIdx.x;
    int is64 = detect64(ei);
    if (tid < 96) sw[tid] = W0[tid];
    if (tid < 32) sb[tid] = b0[tid];
    __syncthreads();
    int i = blockIdx.x * blockDim.x + tid;
    if (i < e) {
        int s = edge_at(ei, i, is64);
        int d = edge_at(ei, e + i, is64);
        int p = atomicAdd(&g_cur[d], 1);
        g_src[p] = s;
    }
    if (i < n * 32) {
        int node = i >> 5, f = i & 31;
        float x0 = x[node * 3 + 0];
        float x1 = x[node * 3 + 1];
        float x2 = x[node * 3 + 2];
        float o = sb[f] + x0 * sw[f] + x1 * sw[32 + f] + x2 * sw[64 + f];
        o = fmaxf(o, 0.f);
        ((float*)g_h)[i] = o;
        ((float*)p_h)[i] = g_dinv[node] * o;
    }
}

// -------- group gather: 8-lane group accumulates one row's [lo,hi), lane = chunk c --------
__device__ __forceinline__ float4 gatherG(const float4* __restrict__ rows,
                                          int lo, int hi, int c) {
    float4 acc = make_float4(0.f, 0.f, 0.f, 0.f);
    int i = lo;
    for (; i + 4 <= hi; i += 4) {
        int s0 = __ldg(&g_src[i]);
        int s1 = __ldg(&g_src[i + 1]);
        int s2 = __ldg(&g_src[i + 2]);
        int s3 = __ldg(&g_src[i + 3]);
        float4 v0 = __ldg(&rows[s0 * 8 + c]);
        float4 v1 = __ldg(&rows[s1 * 8 + c]);
        float4 v2 = __ldg(&rows[s2 * 8 + c]);
        float4 v3 = __ldg(&rows[s3 * 8 + c]);
        acc.x += (v0.x + v1.x) + (v2.x + v3.x);
        acc.y += (v0.y + v1.y) + (v2.y + v3.y);
        acc.z += (v0.z + v1.z) + (v2.z + v3.z);
        acc.w += (v0.w + v1.w) + (v2.w + v3.w);
    }
    for (; i < hi; i++) {
        int s0 = __ldg(&g_src[i]);
        float4 v = __ldg(&rows[s0 * 8 + c]);
        acc.x += v.x; acc.y += v.y; acc.z += v.z; acc.w += v.w;
    }
    return acc;
}

// ---------------- prop: out = L~ in ; warp = 2 rows, 2-way edge split per row ----------------
// in_id: prescaled buffer id (0..3 -> p_*); outA: raw result dest (anybuf id);
// outB: prescaled result dest (anybuf id) or -1.
__global__ void k_prop(int in_id, int outA, int outB, int n) {
    const float4* __restrict__ xin = pbuf(in_id);
    int t = blockIdx.x * blockDim.x + threadIdx.x;
    int lane = threadIdx.x & 31;
    int w = t >> 5;
    int row = (w << 1) + (lane >> 4);
    int sub = (lane >> 3) & 1;
    int c = lane & 7;
    bool valid = row < n;
    int s = 0, e = 0;
    if (valid) { s = g_off[row]; e = g_off[row + 1]; }
    int m = s + ((e - s) >> 1);
    int lo = sub ? m : s;
    int hi = sub ? e : m;
    float4 acc = gatherG(xin, lo, hi, c);
    const unsigned full = 0xffffffffu;
    acc.x += __shfl_xor_sync(full, acc.x, 8);
    acc.y += __shfl_xor_sync(full, acc.y, 8);
    acc.z += __shfl_xor_sync(full, acc.z, 8);
    acc.w += __shfl_xor_sync(full, acc.w, 8);
    if (valid && sub == 0) {
        float di = g_dinv[row];
        float4 r = make_float4(-di * acc.x, -di * acc.y, -di * acc.z, -di * acc.w);
        anybuf(outA)[row * 8 + c] = r;
        if (outB >= 0)
            anybuf(outB)[row * 8 + c] = make_float4(di * r.x, di * r.y, di * r.z, di * r.w);
    }
}

// ---------------- dense Chebyshev combine (P pre-computed, lives in pbuf(out_id)) ----------------
__global__ void __launch_bounds__(256) k_dense(int t0_id, int resid_id, int out_id,
                       const float* __restrict__ Wc, const float* __restrict__ bc, int n) {
    __shared__ float sT[32][100];
    __shared__ float sWt[32][100];
    __shared__ float sO[32][33];
    const float4* __restrict__ t0f = fbuf(t0_id);
    const float4* __restrict__ pf  = pbuf(out_id);   // P = L~ T1 (raw)
    float4* __restrict__ outf = fbuf(out_id);
    float4* __restrict__ outp = pbuf(out_id);

    int tid = threadIdx.x;
    int wid = tid >> 5, lane = tid & 31;
    int base = blockIdx.x << 5;

#pragma unroll
    for (int rep = 0; rep < 12; rep++) {
        int idx = rep * 256 + tid;
        sWt[idx & 31][idx >> 5] = Wc[idx];
    }

    // stage T0 / T1 / T2 = 2P - T0 (3 coalesced float4 loads per thread)
    {
        int nl = tid >> 3, cc = tid & 7;
        int node = base + nl;
        if (node < n) {
            float4 t0 = t0f[node * 8 + cc];
            float4 t1 = g_t[node * 8 + cc];
            float4 P  = pf[node * 8 + cc];
            float4 t2 = make_float4(2.f * P.x - t0.x, 2.f * P.y - t0.y,
                                    2.f * P.z - t0.z, 2.f * P.w - t0.w);
            *(float4*)&sT[nl][cc * 4]      = t0;
            *(float4*)&sT[nl][32 + cc * 4] = t1;
            *(float4*)&sT[nl][64 + cc * 4] = t2;
        }
    }
    __syncthreads();

    // dense phase: warp wid -> features {wid, wid+8, wid+16, wid+24}, node = lane
    {
        float acc0 = __ldg(&bc[wid]);
        float acc1 = __ldg(&bc[wid + 8]);
        float acc2 = __ldg(&bc[wid + 16]);
        float acc3 = __ldg(&bc[wid + 24]);
#pragma unroll
        for (int kc = 0; kc < 24; kc++) {
            float4 t = *(const float4*)&sT[lane][kc * 4];
            float4 w0 = *(const float4*)&sWt[wid][kc * 4];
            float4 w1 = *(const float4*)&sWt[wid + 8][kc * 4];
            float4 w2 = *(const float4*)&sWt[wid + 16][kc * 4];
            float4 w3 = *(const float4*)&sWt[wid + 24][kc * 4];
            acc0 += t.x * w0.x + t.y * w0.y + t.z * w0.z + t.w * w0.w;
            acc1 += t.x * w1.x + t.y * w1.y + t.z * w1.z + t.w * w1.w;
            acc2 += t.x * w2.x + t.y * w2.y + t.z * w2.z + t.w * w2.w;
            acc3 += t.x * w3.x + t.y * w3.y + t.z * w3.z + t.w * w3.w;
        }
        sO[lane][wid]      = acc0;
        sO[lane][wid + 8]  = acc1;
        sO[lane][wid + 16] = acc2;
        sO[lane][wid + 24] = acc3;
    }
    __syncthreads();

    // epilogue: resid + relu + raw/prescaled stores
    {
        int nl = tid >> 3, cc = tid & 7;
        int node = base + nl;
        if (node < n) {
            float4 o;
            o.x = sO[nl][cc * 4 + 0];
            o.y = sO[nl][cc * 4 + 1];
            o.z = sO[nl][cc * 4 + 2];
            o.w = sO[nl][cc * 4 + 3];
            if (resid_id >= 0) {
                float4 rv = fbuf(resid_id)[node * 8 + cc];
                o.x += rv.x; o.y += rv.y; o.z += rv.z; o.w += rv.w;
            }
            o.x = fmaxf(o.x, 0.f); o.y = fmaxf(o.y, 0.f);
            o.z = fmaxf(o.z, 0.f); o.w = fmaxf(o.w, 0.f);
            outf[node * 8 + cc] = o;
            float di = g_dinv[node];
            outp[node * 8 + cc] = make_float4(di * o.x, di * o.y, di * o.z, di * o.w);
        }
    }
}

// ---------------- output layer ----------------
__global__ void k_final(const float* __restrict__ W1, const float* __restrict__ b1,
                        float* __restrict__ out, int n) {
    int node = (blockIdx.x * blockDim.x + threadIdx.x) >> 5;
    int lane = threadIdx.x & 31;
    if (node >= n) return;
    float v = ((const float*)g_h)[node * 32 + lane] * W1[lane];
#pragma unroll
    for (int o = 16; o > 0; o >>= 1) v += __shfl_xor_sync(0xffffffffu, v, o);
    if (lane == 0) out[node] = v + b1[0];
}

// ---------------- launch ----------------
extern "C" void kernel_launch(void* const* d_in, const int* in_sizes, int n_in,
                              void* d_out, int out_size) {
    const float* x    = (const float*)d_in[0];
    const void*  ei   = d_in[1];
    const float* W0   = (const float*)d_in[2];
    const float* b0   = (const float*)d_in[3];
    const float* c11W = (const float*)d_in[4];
    const float* c11b = (const float*)d_in[5];
    const float* c12W = (const float*)d_in[6];
    const float* c12b = (const float*)d_in[7];
    const float* c21W = (const float*)d_in[8];
    const float* c21b = (const float*)d_in[9];
    const float* c22W = (const float*)d_in[10];
    const float* c22b = (const float*)d_in[11];
    const float* W1   = (const float*)d_in[12];
    const float* b1   = (const float*)d_in[13];
    float* out = (float*)d_out;

    int n = in_sizes[0] / 3;
    int e = in_sizes[1] / 2;
    if (n > NN) n = NN;
    if (e > EE) e = EE;

    const int B = 256;
    int gE  = (e + B - 1) / B;
    int gNF = (n * 32 + B - 1) / B;
    int gP  = (n * 16 + B - 1) / B;   // 16 thr/row (2 rows per warp)
    int gT  = (n + 31) / 32;
    int nb  = (n + 1023) / 1024;
    int gSI = (n * 32 > e ? n * 32 : e);
    gSI = (gSI + B - 1) / B;

    // setup: 3 launches -> first k_prop is launch #4 (ncu capture target)
    k_count<<<gE, B>>>(ei, e);
    k_scan<<<nb, 1024>>>(n, nb);
    k_scatin<<<gSI, B>>>(ei, e, x, W0, b0, n);

    // conv(in, out, resid):
    //   k_prop(in, raw->g_t(2), pre->p_t(4+2))
    //   k_prop(t(2), raw->pbuf(out)(4+out), -1)        // P scratch
    //   k_dense(t0=in, resid, out)
    // ids: 0=h, 1=a, 2=t, 3=b

    // conv11: h -> a
    k_prop<<<gP, B>>>(0, 2, 6, n);
    k_prop<<<gP, B>>>(2, 5, -1, n);
    k_dense<<<gT, B>>>(0, -1, 1, c11W, c11b, n);
    // conv12: a -> b, resid h
    k_prop<<<gP, B>>>(1, 2, 6, n);
    k_prop<<<gP, B>>>(2, 7, -1, n);
    k_dense<<<gT, B>>>(1, 0, 3, c12W, c12b, n);
    // conv21: b -> a
    k_prop<<<gP, B>>>(3, 2, 6, n);
    k_prop<<<gP, B>>>(2, 5, -1, n);
    k_dense<<<gT, B>>>(3, -1, 1, c21W, c21b, n);
    // conv22: a -> h, resid b
    k_prop<<<gP, B>>>(1, 2, 6, n);
    k_prop<<<gP, B>>>(2, 4, -1, n);
    k_dense<<<gT, B>>>(1, 3, 0, c22W, c22b, n);

    k_final<<<gNF, B>>>(W1, b1, out, n);
}

// round 9
// speedup vs baseline: 1.5802x; 1.5802x over previous
#include <cuda_runtime.h>

#define NN 200000
#define EE 3200000

// ---------------- static device scratch ----------------
__device__ int      g_deg[NN];
__device__ int      g_cnt[NN];
__device__ float    g_dinv[NN];
__device__ int      g_off[NN + 1];
__device__ int      g_cur[NN];
__device__ unsigned long long g_aggr64[256];
__device__ unsigned g_gen;
__device__ int      g_src[EE];
__device__ float4   g_h[NN * 8];   // raw fp32 features
__device__ float4   g_a[NN * 8];
__device__ float4   g_t[NN * 8];
__device__ float4   g_b[NN * 8];
__device__ float4   p_h[NN * 8];   // pre-scaled (dinv*X)
__device__ float4   p_a[NN * 8];
__device__ float4   p_t[NN * 8];
__device__ float4   p_b[NN * 8];

__device__ __forceinline__ float4* fbuf(int id) {
    switch (id) { case 0: return g_h; case 1: return g_a; case 2: return g_t; default: return g_b; }
}
__device__ __forceinline__ float4* pbuf(int id) {
    switch (id) { case 0: return p_h; case 1: return p_a; case 2: return p_t; default: return p_b; }
}

// per-block dtype detection: 1 if edge buffer is int64
__device__ __forceinline__ int detect64(const void* ei) {
    const int* w = (const int*)ei;
    int bad = 0;
#pragma unroll
    for (int k = 0; k < 2; k++) {
        int idx = (threadIdx.x & 31) + 32 * k;
        if (w[2 * idx + 1] != 0) bad = 1;
    }
    return __all_sync(0xffffffffu, bad == 0) ? 1 : 0;
}

__device__ __forceinline__ int edge_at(const void* ei, int idx, int is64) {
    if (is64) return (int)((const long long*)ei)[idx];
    return ((const int*)ei)[idx];
}

// ---------------- count degrees ----------------
__global__ void k_count(const void* ei, int e) {
    if (blockIdx.x == 0 && threadIdx.x == 0) atomicAdd(&g_gen, 1u);
    int is64 = detect64(ei);
    int i = blockIdx.x * blockDim.x + threadIdx.x;
    if (i < e) {
        int s = edge_at(ei, i, is64);
        int d = edge_at(ei, e + i, is64);
        atomicAdd(&g_deg[s], 1);
        atomicAdd(&g_cnt[d], 1);
    }
}

// ---------------- one-kernel exclusive scan + dinv + reset ----------------
__global__ void k_scan(int n, int nb) {
    __shared__ int sh[1024];
    __shared__ int s_sum;
    int tid = threadIdx.x, b = blockIdx.x;
    int i = b * 1024 + tid;
    if (tid == 0) s_sum = 0;
    int dg = 0, v = 0;
    if (i < n) { dg = g_deg[i]; v = g_cnt[i]; }
    if (i < n) g_dinv[i] = (dg > 0) ? rsqrtf((float)dg) : 0.f;
    sh[tid] = v;
    __syncthreads();
    for (int o = 1; o < 1024; o <<= 1) {
        int t = (tid >= o) ? sh[tid - o] : 0;
        __syncthreads();
        sh[tid] += t;
        __syncthreads();
    }
    unsigned gen = g_gen;
    if (tid == 1023)
        atomicExch(&g_aggr64[b], ((unsigned long long)gen << 32) | (unsigned)sh[1023]);
    if (tid < b) {
        unsigned long long f;
        while (((f = atomicAdd(&g_aggr64[tid], 0ull)) >> 32) != gen) {}
        atomicAdd(&s_sum, (int)(unsigned)f);
    }
    __syncthreads();
    int off = sh[tid] - v + s_sum;
    if (i < n) {
        g_off[i] = off;
        g_cur[i] = off;
        g_deg[i] = 0;
        g_cnt[i] = 0;
        if (i == n - 1) g_off[n] = off + v;
    }
}

// ---------------- fused scatter + input MLP ----------------
__global__ void k_scatin(const void* ei, int e, const float* __restrict__ x,
                         const float* __restrict__ W0, const float* __restrict__ b0, int n) {
    __shared__ float sw[96];
    __shared__ float sb[32];
    int tid = threadIdx.x;
    int is64 = detect64(ei);
    if (tid < 96) sw[tid] = W0[tid];
    if (tid < 32) sb[tid] = b0[tid];
    __syncthreads();
    int i = blockIdx.x * blockDim.x + tid;
    if (i < e) {
        int s = edge_at(ei, i, is64);
        int d = edge_at(ei, e + i, is64);
        int p = atomicAdd(&g_cur[d], 1);
        g_src[p] = s;
    }
    if (i < n * 32) {
        int node = i >> 5, f = i & 31;
        float x0 = x[node * 3 + 0];
        float x1 = x[node * 3 + 1];
        float x2 = x[node * 3 + 2];
        float o = sb[f] + x0 * sw[f] + x1 * sw[32 + f] + x2 * sw[64 + f];
        o = fmaxf(o, 0.f);
        ((float*)g_h)[i] = o;
        ((float*)p_h)[i] = g_dinv[node] * o;
    }
}

// -------- group gather: 8-lane group accumulates one row, lane = float4 chunk c --------
__device__ __forceinline__ float4 gatherG(const float4* __restrict__ rows,
                                          int s, int e, int c) {
    float4 acc = make_float4(0.f, 0.f, 0.f, 0.f);
    int i = s;
    for (; i + 4 <= e; i += 4) {
        int s0 = __ldg(&g_src[i]);
        int s1 = __ldg(&g_src[i + 1]);
        int s2 = __ldg(&g_src[i + 2]);
        int s3 = __ldg(&g_src[i + 3]);
        float4 v0 = __ldg(&rows[s0 * 8 + c]);
        float4 v1 = __ldg(&rows[s1 * 8 + c]);
        float4 v2 = __ldg(&rows[s2 * 8 + c]);
        float4 v3 = __ldg(&rows[s3 * 8 + c]);
        acc.x += (v0.x + v1.x) + (v2.x + v3.x);
        acc.y += (v0.y + v1.y) + (v2.y + v3.y);
        acc.z += (v0.z + v1.z) + (v2.z + v3.z);
        acc.w += (v0.w + v1.w) + (v2.w + v3.w);
    }
    for (; i < e; i++) {
        int s0 = __ldg(&g_src[i]);
        float4 v = __ldg(&rows[s0 * 8 + c]);
        acc.x += v.x; acc.y += v.y; acc.z += v.z; acc.w += v.w;
    }
    return acc;
}

// ---------------- prop: T1 = L~ x ; warp = 4 rows, 8-lane group per row (R7 proven) ----------------
__global__ void k_prop(int in_id, int n) {
    const float4* __restrict__ xin = pbuf(in_id);
    int t = blockIdx.x * blockDim.x + threadIdx.x;
    int lane = threadIdx.x & 31;
    int row = ((t >> 5) << 2) + (lane >> 3);
    int c = lane & 7;
    if (row >= n) return;
    int s = g_off[row], e = g_off[row + 1];
    float4 acc = gatherG(xin, s, e, c);
    float di = g_dinv[row];
    float4 r = make_float4(-di * acc.x, -di * acc.y, -di * acc.z, -di * acc.w);
    g_t[row * 8 + c] = r;
    p_t[row * 8 + c] = make_float4(di * r.x, di * r.y, di * r.z, di * r.w);
}

// ---------------- fused second prop + warp-autonomous Chebyshev combine ----------------
// warp handles 4 nodes end-to-end: gather -> sT slice -> syncwarp -> dense -> store.
__global__ void __launch_bounds__(256) k_comb(int t0_id, int resid_id, int out_id,
                       const float* __restrict__ Wc, const float* __restrict__ bc, int n) {
    __shared__ float sW[3072];          // natural [k][f] layout (no transpose)
    __shared__ float sT[8][4][100];     // per-warp: 4 nodes x [t0|t1|t2] (pitch 100)
    const float4* __restrict__ t0f = fbuf(t0_id);
    float4* __restrict__ outf = fbuf(out_id);
    float4* __restrict__ outp = pbuf(out_id);
    const float4* __restrict__ bc4 = (const float4*)bc;

    int tid = threadIdx.x;
    int wid = tid >> 5, lane = tid & 31;
    int grp = lane >> 3, c = lane & 7;      // gather: group = node, c = chunk
    int base = (blockIdx.x << 5) + (wid << 2);

    // weight preload (one block-wide sync, before any divergent work)
#pragma unroll
    for (int rep = 0; rep < 12; rep++) sW[rep * 256 + tid] = Wc[rep * 256 + tid];
    __syncthreads();

    // gather phase: this warp's node grp
    int node = base + grp;
    if (node < n) {
        int s = g_off[node], e = g_off[node + 1];
        float4 acc = gatherG(p_t, s, e, c);
        float di = g_dinv[node];
        float4 t0 = t0f[node * 8 + c];
        float4 t1 = g_t[node * 8 + c];
        float m = -2.f * di;
        float4 t2;
        t2.x = fmaf(m, acc.x, -t0.x);
        t2.y = fmaf(m, acc.y, -t0.y);
        t2.z = fmaf(m, acc.z, -t0.z);
        t2.w = fmaf(m, acc.w, -t0.w);
        *(float4*)&sT[wid][grp][c * 4]      = t0;
        *(float4*)&sT[wid][grp][32 + c * 4] = t1;
        *(float4*)&sT[wid][grp][64 + c * 4] = t2;
    }
    __syncwarp();

    // dense phase: lane -> (node grp, feature chunk c): out[node][c*4 .. c*4+3]
    if (node < n) {
        float4 a = __ldg(&bc4[c]);
#pragma unroll
        for (int kq = 0; kq < 24; kq++) {
            float4 t = *(const float4*)&sT[wid][grp][kq * 4];
            float4 w0 = *(const float4*)&sW[(kq * 4 + 0) * 32 + c * 4];
            float4 w1 = *(const float4*)&sW[(kq * 4 + 1) * 32 + c * 4];
            float4 w2 = *(const float4*)&sW[(kq * 4 + 2) * 32 + c * 4];
            float4 w3 = *(const float4*)&sW[(kq * 4 + 3) * 32 + c * 4];
            a.x += t.x * w0.x + t.y * w1.x + t.z * w2.x + t.w * w3.x;
            a.y += t.x * w0.y + t.y * w1.y + t.z * w2.y + t.w * w3.y;
            a.z += t.x * w0.z + t.y * w1.z + t.z * w2.z + t.w * w3.z;
            a.w += t.x * w0.w + t.y * w1.w + t.z * w2.w + t.w * w3.w;
        }
        if (resid_id >= 0) {
            float4 rv = fbuf(resid_id)[node * 8 + c];
            a.x += rv.x; a.y += rv.y; a.z += rv.z; a.w += rv.w;
        }
        a.x = fmaxf(a.x, 0.f); a.y = fmaxf(a.y, 0.f);
        a.z = fmaxf(a.z, 0.f); a.w = fmaxf(a.w, 0.f);
        outf[node * 8 + c] = a;
        float di = g_dinv[node];
        outp[node * 8 + c] = make_float4(di * a.x, di * a.y, di * a.z, di * a.w);
    }
}

// ---------------- output layer ----------------
__global__ void k_final(const float* __restrict__ W1, const float* __restrict__ b1,
                        float* __restrict__ out, int n) {
    int node = (blockIdx.x * blockDim.x + threadIdx.x) >> 5;
    int lane = threadIdx.x & 31;
    if (node >= n) return;
    float v = ((const float*)g_h)[node * 32 + lane] * W1[lane];
#pragma unroll
    for (int o = 16; o > 0; o >>= 1) v += __shfl_xor_sync(0xffffffffu, v, o);
    if (lane == 0) out[node] = v + b1[0];
}

// ---------------- launch ----------------
extern "C" void kernel_launch(void* const* d_in, const int* in_sizes, int n_in,
                              void* d_out, int out_size) {
    const float* x    = (const float*)d_in[0];
    const void*  ei   = d_in[1];
    const float* W0   = (const float*)d_in[2];
    const float* b0   = (const float*)d_in[3];
    const float* c11W = (const float*)d_in[4];
    const float* c11b = (const float*)d_in[5];
    const float* c12W = (const float*)d_in[6];
    const float* c12b = (const float*)d_in[7];
    const float* c21W = (const float*)d_in[8];
    const float* c21b = (const float*)d_in[9];
    const float* c22W = (const float*)d_in[10];
    const float* c22b = (const float*)d_in[11];
    const float* W1   = (const float*)d_in[12];
    const float* b1   = (const float*)d_in[13];
    float* out = (float*)d_out;

    int n = in_sizes[0] / 3;
    int e = in_sizes[1] / 2;
    if (n > NN) n = NN;
    if (e > EE) e = EE;

    const int B = 256;
    int gE  = (e + B - 1) / B;
    int gNF = (n * 32 + B - 1) / B;   // 32 thr/node
    int gP  = (n * 8 + B - 1) / B;    // 8 thr/row (prop)
    int gT  = (n + 31) / 32;          // 32-node tiles
    int nb  = (n + 1023) / 1024;
    int gSI = (n * 32 > e ? n * 32 : e);
    gSI = (gSI + B - 1) / B;

    // setup: 3 launches -> first k_prop is launch #4 (ncu capture target)
    k_count<<<gE, B>>>(ei, e);
    k_scan<<<nb, 1024>>>(n, nb);
    k_scatin<<<gSI, B>>>(ei, e, x, W0, b0, n);

    // ids: 0=h, 1=a, 2=t, 3=b
    k_prop<<<gP, B>>>(0, n);
    k_comb<<<gT, B>>>(0, -1, 1, c11W, c11b, n);
    k_prop<<<gP, B>>>(1, n);
    k_comb<<<gT, B>>>(1, 0, 3, c12W, c12b, n);
    k_prop<<<gP, B>>>(3, n);
    k_comb<<<gT, B>>>(3, -1, 1, c21W, c21b, n);
    k_prop<<<gP, B>>>(1, n);
    k_comb<<<gT, B>>>(1, 3, 0, c22W, c22b, n);

    k_final<<<gNF, B>>>(W1, b1, out, n);
}

// round 10
// speedup vs baseline: 1.7798x; 1.1263x over previous
#include <cuda_runtime.h>

#define NN 200000
#define EE 3200000
#define EP (EE + 3 * NN + 4)   // padded edge capacity

// ---------------- static device scratch ----------------
__device__ int      g_deg[NN];
__device__ int      g_cnt[NN];
__device__ float    g_dinv[NN];
__device__ int      g_off[NN + 1];
__device__ int      g_cur[NN];
__device__ unsigned long long g_aggr64[256];
__device__ unsigned g_gen;
__device__ int      g_src[EP];
__device__ float4   g_h[NN * 8];         // raw fp32 features
__device__ float4   g_a[NN * 8];
__device__ float4   g_t[NN * 8];
__device__ float4   g_b[NN * 8];
__device__ float4   p_h[(NN + 1) * 8];   // pre-scaled (dinv*X); row NN stays zero (pad target)
__device__ float4   p_a[(NN + 1) * 8];
__device__ float4   p_t[(NN + 1) * 8];
__device__ float4   p_b[(NN + 1) * 8];

__device__ __forceinline__ float4* fbuf(int id) {
    switch (id) { case 0: return g_h; case 1: return g_a; case 2: return g_t; default: return g_b; }
}
__device__ __forceinline__ float4* pbuf(int id) {
    switch (id) { case 0: return p_h; case 1: return p_a; case 2: return p_t; default: return p_b; }
}

// per-block dtype detection: 1 if edge buffer is int64
__device__ __forceinline__ int detect64(const void* ei) {
    const int* w = (const int*)ei;
    int bad = 0;
#pragma unroll
    for (int k = 0; k < 2; k++) {
        int idx = (threadIdx.x & 31) + 32 * k;
        if (w[2 * idx + 1] != 0) bad = 1;
    }
    return __all_sync(0xffffffffu, bad == 0) ? 1 : 0;
}

__device__ __forceinline__ int edge_at(const void* ei, int idx, int is64) {
    if (is64) return (int)((const long long*)ei)[idx];
    return ((const int*)ei)[idx];
}

// ---------------- count degrees ----------------
__global__ void k_count(const void* ei, int e) {
    if (blockIdx.x == 0 && threadIdx.x == 0) atomicAdd(&g_gen, 1u);
    int is64 = detect64(ei);
    int i = blockIdx.x * blockDim.x + threadIdx.x;
    if (i < e) {
        int s = edge_at(ei, i, is64);
        int d = edge_at(ei, e + i, is64);
        atomicAdd(&g_deg[s], 1);
        atomicAdd(&g_cnt[d], 1);
    }
}

// ---------------- one-kernel exclusive scan over PADDED counts + dinv + pad-fill + reset ----------------
__global__ void k_scan(int n, int nb) {
    __shared__ int sh[1024];
    __shared__ int s_sum;
    int tid = threadIdx.x, b = blockIdx.x;
    int i = b * 1024 + tid;
    if (tid == 0) s_sum = 0;
    int dg = 0, v = 0;
    if (i < n) { dg = g_deg[i]; v = g_cnt[i]; }
    if (i < n) g_dinv[i] = (dg > 0) ? rsqrtf((float)dg) : 0.f;
    int pv = (v + 3) & ~3;          // padded row length (multiple of 4)
    sh[tid] = pv;
    __syncthreads();
    for (int o = 1; o < 1024; o <<= 1) {
        int t = (tid >= o) ? sh[tid - o] : 0;
        __syncthreads();
        sh[tid] += t;
        __syncthreads();
    }
    unsigned gen = g_gen;
    if (tid == 1023)
        atomicExch(&g_aggr64[b], ((unsigned long long)gen << 32) | (unsigned)sh[1023]);
    if (tid < b) {
        unsigned long long f;
        while (((f = atomicAdd(&g_aggr64[tid], 0ull)) >> 32) != gen) {}
        atomicAdd(&s_sum, (int)(unsigned)f);
    }
    __syncthreads();
    int off = sh[tid] - pv + s_sum;   // padded exclusive prefix
    if (i < n) {
        g_off[i] = off;
        g_cur[i] = off;
        for (int j = v; j < pv; j++) g_src[off + j] = n;   // pad -> zero row
        g_deg[i] = 0;
        g_cnt[i] = 0;
        if (i == n - 1) g_off[n] = off + pv;
    }
}

// ---------------- fused scatter + input MLP ----------------
__global__ void k_scatin(const void* ei, int e, const float* __restrict__ x,
                         const float* __restrict__ W0, const float* __restrict__ b0, int n) {
    __shared__ float sw[96];
    __shared__ float sb[32];
    int tid = threadIdx.x;
    int is64 = detect64(ei);
    if (tid < 96) sw[tid] = W0[tid];
    if (tid < 32) sb[tid] = b0[tid];
    __syncthreads();
    int i = blockIdx.x * blockDim.x + tid;
    if (i < e) {
        int s = edge_at(ei, i, is64);
        int d = edge_at(ei, e + i, is64);
        int p = atomicAdd(&g_cur[d], 1);
        g_src[p] = s;
    }
    if (i < n * 32) {
        int node = i >> 5, f = i & 31;
        float x0 = x[node * 3 + 0];
        float x1 = x[node * 3 + 1];
        float x2 = x[node * 3 + 2];
        float o = sb[f] + x0 * sw[f] + x1 * sw[32 + f] + x2 * sw[64 + f];
        o = fmaxf(o, 0.f);
        ((float*)g_h)[i] = o;
        ((float*)p_h)[i] = g_dinv[node] * o;
    }
}

// -------- group gather (padded): 8-lane group accumulates one row; int4 index loads, no tail --------
__device__ __forceinline__ float4 gatherP(const float4* __restrict__ rows,
                                          int s, int e, int c) {
    float4 acc = make_float4(0.f, 0.f, 0.f, 0.f);
    for (int i = s; i < e; i += 4) {
        int4 ix = __ldg((const int4*)&g_src[i]);
        float4 v0 = __ldg(&rows[ix.x * 8 + c]);
        float4 v1 = __ldg(&rows[ix.y * 8 + c]);
        float4 v2 = __ldg(&rows[ix.z * 8 + c]);
        float4 v3 = __ldg(&rows[ix.w * 8 + c]);
        acc.x += (v0.x + v1.x) + (v2.x + v3.x);
        acc.y += (v0.y + v1.y) + (v2.y + v3.y);
        acc.z += (v0.z + v1.z) + (v2.z + v3.z);
        acc.w += (v0.w + v1.w) + (v2.w + v3.w);
    }
    return acc;
}

// ---------------- prop: T1 = L~ x ; warp = 4 rows, 8-lane group per row ----------------
__global__ void k_prop(int in_id, int n) {
    const float4* __restrict__ xin = pbuf(in_id);
    int t = blockIdx.x * blockDim.x + threadIdx.x;
    int lane = threadIdx.x & 31;
    int row = ((t >> 5) << 2) + (lane >> 3);
    int c = lane & 7;
    if (row >= n) return;
    int s = g_off[row], e = g_off[row + 1];
    float4 acc = gatherP(xin, s, e, c);
    float di = g_dinv[row];
    float4 r = make_float4(-di * acc.x, -di * acc.y, -di * acc.z, -di * acc.w);
    g_t[row * 8 + c] = r;
    p_t[row * 8 + c] = make_float4(di * r.x, di * r.y, di * r.z, di * r.w);
}

// ---------------- fused second prop + tiled Chebyshev combine (R7 structure) ----------------
__global__ void __launch_bounds__(256) k_comb(int t0_id, int resid_id, int out_id,
                       const float* __restrict__ Wc, const float* __restrict__ bc, int n) {
    __shared__ float sT[32][100];
    __shared__ float sWt[32][100];
    __shared__ float sO[32][33];
    const float4* __restrict__ t0f = fbuf(t0_id);
    float4* __restrict__ outf = fbuf(out_id);
    float4* __restrict__ outp = pbuf(out_id);

    int tid = threadIdx.x;
    int wid = tid >> 5, lane = tid & 31;
    int base = blockIdx.x << 5;

#pragma unroll
    for (int rep = 0; rep < 12; rep++) {
        int idx = rep * 256 + tid;
        sWt[idx & 31][idx >> 5] = Wc[idx];
    }

    // gather phase: warp's 4 groups = 4 nodes
    {
        int grp = lane >> 3, c = lane & 7;
        int nl = (wid << 2) + grp;
        int node = base + nl;
        if (node < n) {
            int s = g_off[node], e = g_off[node + 1];
            float4 acc = gatherP(p_t, s, e, c);
            float di = g_dinv[node];
            float4 t0 = t0f[node * 8 + c];
            float4 t1 = g_t[node * 8 + c];
            float m = -2.f * di;
            float4 t2;
            t2.x = fmaf(m, acc.x, -t0.x);
            t2.y = fmaf(m, acc.y, -t0.y);
            t2.z = fmaf(m, acc.z, -t0.z);
            t2.w = fmaf(m, acc.w, -t0.w);
            *(float4*)&sT[nl][c * 4]      = t0;
            *(float4*)&sT[nl][32 + c * 4] = t1;
            *(float4*)&sT[nl][64 + c * 4] = t2;
        }
    }
    __syncthreads();

    // dense phase: warp wid -> features {wid, wid+8, wid+16, wid+24}, node = lane
    {
        float acc0 = __ldg(&bc[wid]);
        float acc1 = __ldg(&bc[wid + 8]);
        float acc2 = __ldg(&bc[wid + 16]);
        float acc3 = __ldg(&bc[wid + 24]);
#pragma unroll
        for (int kc = 0; kc < 24; kc++) {
            float4 t = *(const float4*)&sT[lane][kc * 4];
            float4 w0 = *(const float4*)&sWt[wid][kc * 4];
            float4 w1 = *(const float4*)&sWt[wid + 8][kc * 4];
            float4 w2 = *(const float4*)&sWt[wid + 16][kc * 4];
            float4 w3 = *(const float4*)&sWt[wid + 24][kc * 4];
            acc0 += t.x * w0.x + t.y * w0.y + t.z * w0.z + t.w * w0.w;
            acc1 += t.x * w1.x + t.y * w1.y + t.z * w1.z + t.w * w1.w;
            acc2 += t.x * w2.x + t.y * w2.y + t.z * w2.z + t.w * w2.w;
            acc3 += t.x * w3.x + t.y * w3.y + t.z * w3.z + t.w * w3.w;
        }
        sO[lane][wid]      = acc0;
        sO[lane][wid + 8]  = acc1;
        sO[lane][wid + 16] = acc2;
        sO[lane][wid + 24] = acc3;
    }
    __syncthreads();

    // epilogue: resid + relu + raw/prescaled stores
    {
        int nl = tid >> 3, cc = tid & 7;
        int node = base + nl;
        if (node < n) {
            float4 o;
            o.x = sO[nl][cc * 4 + 0];
            o.y = sO[nl][cc * 4 + 1];
            o.z = sO[nl][cc * 4 + 2];
            o.w = sO[nl][cc * 4 + 3];
            if (resid_id >= 0) {
                float4 rv = fbuf(resid_id)[node * 8 + cc];
                o.x += rv.x; o.y += rv.y; o.z += rv.z; o.w += rv.w;
            }
            o.x = fmaxf(o.x, 0.f); o.y = fmaxf(o.y, 0.f);
            o.z = fmaxf(o.z, 0.f); o.w = fmaxf(o.w, 0.f);
            outf[node * 8 + cc] = o;
            float di = g_dinv[node];
            outp[node * 8 + cc] = make_float4(di * o.x, di * o.y, di * o.z, di * o.w);
        }
    }
}

// ---------------- output layer ----------------
__global__ void k_final(const float* __restrict__ W1, const float* __restrict__ b1,
                        float* __restrict__ out, int n) {
    int node = (blockIdx.x * blockDim.x + threadIdx.x) >> 5;
    int lane = threadIdx.x & 31;
    if (node >= n) return;
    float v = ((const float*)g_h)[node * 32 + lane] * W1[lane];
#pragma unroll
    for (int o = 16; o > 0; o >>= 1) v += __shfl_xor_sync(0xffffffffu, v, o);
    if (lane == 0) out[node] = v + b1[0];
}

// ---------------- launch ----------------
extern "C" void kernel_launch(void* const* d_in, const int* in_sizes, int n_in,
                              void* d_out, int out_size) {
    const float* x    = (const float*)d_in[0];
    const void*  ei   = d_in[1];
    const float* W0   = (const float*)d_in[2];
    const float* b0   = (const float*)d_in[3];
    const float* c11W = (const float*)d_in[4];
    const float* c11b = (const float*)d_in[5];
    const float* c12W = (const float*)d_in[6];
    const float* c12b = (const float*)d_in[7];
    const float* c21W = (const float*)d_in[8];
    const float* c21b = (const float*)d_in[9];
    const float* c22W = (const float*)d_in[10];
    const float* c22b = (const float*)d_in[11];
    const float* W1   = (const float*)d_in[12];
    const float* b1   = (const float*)d_in[13];
    float* out = (float*)d_out;

    int n = in_sizes[0] / 3;
    int e = in_sizes[1] / 2;
    if (n > NN) n = NN;
    if (e > EE) e = EE;

    const int B = 256;
    int gE  = (e + B - 1) / B;
    int gNF = (n * 32 + B - 1) / B;   // 32 thr/node
    int gP  = (n * 8 + B - 1) / B;    // 8 thr/row (prop)
    int gT  = (n + 31) / 32;          // 32-node tiles
    int nb  = (n + 1023) / 1024;
    int gSI = (n * 32 > e ? n * 32 : e);
    gSI = (gSI + B - 1) / B;

    // setup: 3 launches -> first k_prop is launch #4 (ncu capture target)
    k_count<<<gE, B>>>(ei, e);
    k_scan<<<nb, 1024>>>(n, nb);
    k_scatin<<<gSI, B>>>(ei, e, x, W0, b0, n);

    // ids: 0=h, 1=a, 2=t, 3=b
    k_prop<<<gP, B>>>(0, n);
    k_comb<<<gT, B>>>(0, -1, 1, c11W, c11b, n);
    k_prop<<<gP, B>>>(1, n);
    k_comb<<<gT, B>>>(1, 0, 3, c12W, c12b, n);
    k_prop<<<gP, B>>>(3, n);
    k_comb<<<gT, B>>>(3, -1, 1, c21W, c21b, n);
    k_prop<<<gP, B>>>(1, n);
    k_comb<<<gT, B>>>(1, 3, 0, c22W, c22b, n);

    k_final<<<gNF, B>>>(W1, b1, out, n);
}